// round 5
// baseline (speedup 1.0000x reference)
#include <cuda_runtime.h>
#include <cstdint>

// Problem constants (fixed by the reference): D=64, K=1024, N=65536.
#define DIM   64
#define MBLK  128          // rows per CTA
#define NBLK  128          // codes per smem tile
#define TM    8            // rows per thread
#define TN    8            // codes per thread
#define MAXK  4096

__device__ float g_c2[MAXK];   // ||w_k||^2, sequential fp32 sum

// Packed fp32x2 fused multiply-add (FFMA2). Each half is an IEEE fp32 FMA,
// so per-output accumulation chains are bit-identical to scalar fmaf chains.
__device__ __forceinline__ unsigned long long ffma2(unsigned long long a,
                                                    unsigned long long b,
                                                    unsigned long long c) {
    unsigned long long d;
    asm("fma.rn.f32x2 %0, %1, %2, %3;" : "=l"(d) : "l"(a), "l"(b), "l"(c));
    return d;
}

// ---------------------------------------------------------------------------
// C2[k] = sum_d W[k][d]^2, sequential (mul then add, round-to-nearest each op)
// ---------------------------------------------------------------------------
__global__ void c2_kernel(const float* __restrict__ W, int K) {
    int k = blockIdx.x * blockDim.x + threadIdx.x;
    if (k >= K) return;
    const float* w = W + k * DIM;
    float s = 0.0f;
#pragma unroll
    for (int d = 0; d < DIM; ++d)
        s = __fadd_rn(s, __fmul_rn(w[d], w[d]));
    g_c2[k] = s;
}

// ---------------------------------------------------------------------------
// Main VQ kernel: per-CTA 128 rows vs all K codes.
// dist = ((L2 - 2*dot) + C2) in fp32, argmin with first-index tie-break.
// ---------------------------------------------------------------------------
__global__ void __launch_bounds__(256, 2)
vq_kernel(const float* __restrict__ X, const float* __restrict__ W,
          float* __restrict__ outQ, float* __restrict__ outI, int K)
{
    extern __shared__ float smem[];
    float* xs  = smem;                              // [DIM][MBLK]      8192 f
    float* ws  = smem + DIM * MBLK;                 // [DIM][2*NBLK]   16384 f (dup codes)
    float* l2s = smem + DIM * MBLK + DIM * 2 * NBLK; // [MBLK]           128 f

    const int tid = threadIdx.x;
    const int tx  = tid & 15;        // code group
    const int ty  = tid >> 4;        // row group
    const int rowbase = blockIdx.x * MBLK;

    // ---- load X tile, transposed into xs[d][m] ----
    {
        int r = tid >> 1, h = tid & 1;
        const float4* src = (const float4*)(X + (size_t)(rowbase + r) * DIM + h * 32);
#pragma unroll
        for (int q = 0; q < 8; ++q) {
            float4 v = src[q];
            int d = h * 32 + q * 4;
            xs[(d + 0) * MBLK + r] = v.x;
            xs[(d + 1) * MBLK + r] = v.y;
            xs[(d + 2) * MBLK + r] = v.z;
            xs[(d + 3) * MBLK + r] = v.w;
        }
    }
    __syncthreads();

    // ---- L2 per row: sequential fp32 (mul, then add) ----
    if (tid < MBLK) {
        float s = 0.0f;
#pragma unroll
        for (int d = 0; d < DIM; ++d) {
            float v = xs[d * MBLK + tid];
            s = __fadd_rn(s, __fmul_rn(v, v));
        }
        l2s[tid] = s;
    }
    __syncthreads();

    float l2r[TM];
#pragma unroll
    for (int r = 0; r < TM; ++r) l2r[r] = l2s[ty * TM + r];

    float bestd[TM];
    int   besti[TM];
#pragma unroll
    for (int r = 0; r < TM; ++r) { bestd[r] = 3.4e38f; besti[r] = 0; }

    const int ntiles = K / NBLK;
    for (int t = 0; t < ntiles; ++t) {
        const int cb = t * NBLK;

        // ---- load W tile, transposed + duplicated: ws[d][2c]=ws[d][2c+1]=W[cb+c][d]
        {
            int c = tid >> 1, h = tid & 1;
            const float4* src = (const float4*)(W + (size_t)(cb + c) * DIM + h * 32);
#pragma unroll
            for (int q = 0; q < 8; ++q) {
                float4 v = src[q];
                int d = h * 32 + q * 4;
                ws[(d + 0) * (2 * NBLK) + 2 * c] = v.x; ws[(d + 0) * (2 * NBLK) + 2 * c + 1] = v.x;
                ws[(d + 1) * (2 * NBLK) + 2 * c] = v.y; ws[(d + 1) * (2 * NBLK) + 2 * c + 1] = v.y;
                ws[(d + 2) * (2 * NBLK) + 2 * c] = v.z; ws[(d + 2) * (2 * NBLK) + 2 * c + 1] = v.z;
                ws[(d + 3) * (2 * NBLK) + 2 * c] = v.w; ws[(d + 3) * (2 * NBLK) + 2 * c + 1] = v.w;
            }
        }
        __syncthreads();

        // ---- mainloop: 8 rows x 8 codes per thread, FFMA2 over packed row-pairs
        unsigned long long acc[4][8];
#pragma unroll
        for (int p = 0; p < 4; ++p)
#pragma unroll
            for (int j = 0; j < 8; ++j) acc[p][j] = 0ull;   // (0.f, 0.f)

        const float* px = xs + ty * TM;
        const float* pw = ws + tx * 16;
#pragma unroll 8
        for (int d = 0; d < DIM; ++d) {
            ulonglong2 xa = *(const ulonglong2*)(px);
            ulonglong2 xb = *(const ulonglong2*)(px + 4);
            ulonglong2 w0 = *(const ulonglong2*)(pw);
            ulonglong2 w1 = *(const ulonglong2*)(pw + 4);
            ulonglong2 w2 = *(const ulonglong2*)(pw + 8);
            ulonglong2 w3 = *(const ulonglong2*)(pw + 12);
            px += MBLK; pw += 2 * NBLK;
            unsigned long long xv[4] = {xa.x, xa.y, xb.x, xb.y};
            unsigned long long wv[8] = {w0.x, w0.y, w1.x, w1.y, w2.x, w2.y, w3.x, w3.y};
#pragma unroll
            for (int p = 0; p < 4; ++p)
#pragma unroll
                for (int j = 0; j < 8; ++j)
                    acc[p][j] = ffma2(xv[p], wv[j], acc[p][j]);
        }

        // ---- per-tile epilogue: distances + running argmin (codes ascending)
#pragma unroll
        for (int j = 0; j < 8; ++j) {
            int code = cb + tx * TN + j;
            float c2 = __ldg(&g_c2[code]);
#pragma unroll
            for (int p = 0; p < 4; ++p) {
                float lo = __uint_as_float((unsigned)(acc[p][j] & 0xffffffffull));
                float hi = __uint_as_float((unsigned)(acc[p][j] >> 32));
                int r0 = 2 * p, r1 = 2 * p + 1;
                float d0 = __fadd_rn(__fsub_rn(l2r[r0], __fmul_rn(2.0f, lo)), c2);
                float d1 = __fadd_rn(__fsub_rn(l2r[r1], __fmul_rn(2.0f, hi)), c2);
                if (d0 < bestd[r0]) { bestd[r0] = d0; besti[r0] = code; }
                if (d1 < bestd[r1]) { bestd[r1] = d1; besti[r1] = code; }
            }
        }
        __syncthreads();   // ws reuse next tile
    }

    // ---- cross-thread reduction over the 16 code groups (tx), padded stride 17
    float* redD = ws;                       // 128*17 floats
    int*   redI = (int*)(ws + 128 * 17);    // 128*17 ints
    int*   bidx = (int*)(ws + 2 * 128 * 17);
#pragma unroll
    for (int r = 0; r < TM; ++r) {
        int row = ty * TM + r;
        redD[row * 17 + tx] = bestd[r];
        redI[row * 17 + tx] = besti[r];
    }
    __syncthreads();

    if (tid < MBLK) {
        float bd = redD[tid * 17];
        int   bi = redI[tid * 17];
#pragma unroll
        for (int u = 1; u < 16; ++u) {
            float dv = redD[tid * 17 + u];
            int   iv = redI[tid * 17 + u];
            if (dv < bd || (dv == bd && iv < bi)) { bd = dv; bi = iv; }
        }
        bidx[tid] = bi;
        if (outI) outI[rowbase + tid] = (float)bi;
    }
    __syncthreads();

    // ---- gather quantized = W[closest]
    if (outQ) {
        int r = tid >> 1, h = tid & 1;
        int idx = bidx[r];
        const float4* src = (const float4*)(W + (size_t)idx * DIM + h * 32);
        float4* dst = (float4*)(outQ + (size_t)(rowbase + r) * DIM + h * 32);
#pragma unroll
        for (int q = 0; q < 8; ++q) dst[q] = __ldg(src + q);
    }
}

// ---------------------------------------------------------------------------
extern "C" void kernel_launch(void* const* d_in, const int* in_sizes, int n_in,
                              void* d_out, int out_size) {
    const float* X = (const float*)d_in[0];
    const float* W = (const float*)d_in[1];
    int N = in_sizes[0] / DIM;
    int K = in_sizes[1] / DIM;

    long long nd = (long long)N * DIM;
    float* outQ = nullptr;
    float* outI = nullptr;
    if ((long long)out_size >= nd + N) { outQ = (float*)d_out; outI = (float*)d_out + nd; }
    else if ((long long)out_size == nd) { outQ = (float*)d_out; }
    else { outI = (float*)d_out; }

    size_t smembytes = (size_t)(DIM * MBLK + DIM * 2 * NBLK + MBLK) * sizeof(float);
    cudaFuncSetAttribute(vq_kernel, cudaFuncAttributeMaxDynamicSharedMemorySize,
                         (int)smembytes);

    c2_kernel<<<(K + 255) / 256, 256>>>(W, K);
    vq_kernel<<<N / MBLK, 256, smembytes>>>(X, W, outQ, outI, K);
}

// round 6
// speedup vs baseline: 1.0009x; 1.0009x over previous
#include <cuda_runtime.h>
#include <cstdint>

// Problem constants (fixed by the reference): D=64, K=1024, N=65536.
#define DIM   64
#define MBLK  128          // rows per CTA
#define NBLK  128          // codes per smem tile
#define TM    8            // rows per thread
#define TN    8            // codes per thread
#define MAXK  4096

__device__ float g_c2[MAXK];   // ||w_k||^2, sequential fp32 sum

// Packed fp32x2 fused multiply-add (FFMA2). Each half is an IEEE fp32 FMA,
// so per-output accumulation chains are bit-identical to scalar fmaf chains.
__device__ __forceinline__ unsigned long long ffma2(unsigned long long a,
                                                    unsigned long long b,
                                                    unsigned long long c) {
    unsigned long long d;
    asm("fma.rn.f32x2 %0, %1, %2, %3;" : "=l"(d) : "l"(a), "l"(b), "l"(c));
    return d;
}

// ---------------------------------------------------------------------------
// C2[k] = sum_d W[k][d]^2, sequential (mul then add, round-to-nearest each op)
// ---------------------------------------------------------------------------
__global__ void c2_kernel(const float* __restrict__ W, int K) {
    int k = blockIdx.x * blockDim.x + threadIdx.x;
    if (k >= K) return;
    const float* w = W + k * DIM;
    float s = 0.0f;
#pragma unroll
    for (int d = 0; d < DIM; ++d)
        s = __fadd_rn(s, __fmul_rn(w[d], w[d]));
    g_c2[k] = s;
}

// ---------------------------------------------------------------------------
// Main VQ kernel: per-CTA 128 rows vs all K codes.
// dist = ((L2 - 2*dot) + C2) in fp32, argmin with first-index tie-break.
// ---------------------------------------------------------------------------
__global__ void __launch_bounds__(256, 2)
vq_kernel(const float* __restrict__ X, const float* __restrict__ W,
          float* __restrict__ outQ, float* __restrict__ outI, int K)
{
    extern __shared__ float smem[];
    float* xs  = smem;                              // [DIM][MBLK]      8192 f
    float* ws  = smem + DIM * MBLK;                 // [DIM][2*NBLK]   16384 f (dup codes)
    float* l2s = smem + DIM * MBLK + DIM * 2 * NBLK; // [MBLK]           128 f

    const int tid = threadIdx.x;
    const int tx  = tid & 15;        // code group
    const int ty  = tid >> 4;        // row group
    const int rowbase = blockIdx.x * MBLK;

    // ---- load X tile, transposed into xs[d][m] ----
    {
        int r = tid >> 1, h = tid & 1;
        const float4* src = (const float4*)(X + (size_t)(rowbase + r) * DIM + h * 32);
#pragma unroll
        for (int q = 0; q < 8; ++q) {
            float4 v = src[q];
            int d = h * 32 + q * 4;
            xs[(d + 0) * MBLK + r] = v.x;
            xs[(d + 1) * MBLK + r] = v.y;
            xs[(d + 2) * MBLK + r] = v.z;
            xs[(d + 3) * MBLK + r] = v.w;
        }
    }
    __syncthreads();

    // ---- L2 per row: sequential fp32 (mul, then add) ----
    if (tid < MBLK) {
        float s = 0.0f;
#pragma unroll
        for (int d = 0; d < DIM; ++d) {
            float v = xs[d * MBLK + tid];
            s = __fadd_rn(s, __fmul_rn(v, v));
        }
        l2s[tid] = s;
    }
    __syncthreads();

    float l2r[TM];
#pragma unroll
    for (int r = 0; r < TM; ++r) l2r[r] = l2s[ty * TM + r];

    float bestd[TM];
    int   besti[TM];
#pragma unroll
    for (int r = 0; r < TM; ++r) { bestd[r] = 3.4e38f; besti[r] = 0; }

    const int ntiles = K / NBLK;
    for (int t = 0; t < ntiles; ++t) {
        const int cb = t * NBLK;

        // ---- load W tile, transposed + duplicated: ws[d][2c]=ws[d][2c+1]=W[cb+c][d]
        {
            int c = tid >> 1, h = tid & 1;
            const float4* src = (const float4*)(W + (size_t)(cb + c) * DIM + h * 32);
#pragma unroll
            for (int q = 0; q < 8; ++q) {
                float4 v = src[q];
                int d = h * 32 + q * 4;
                ws[(d + 0) * (2 * NBLK) + 2 * c] = v.x; ws[(d + 0) * (2 * NBLK) + 2 * c + 1] = v.x;
                ws[(d + 1) * (2 * NBLK) + 2 * c] = v.y; ws[(d + 1) * (2 * NBLK) + 2 * c + 1] = v.y;
                ws[(d + 2) * (2 * NBLK) + 2 * c] = v.z; ws[(d + 2) * (2 * NBLK) + 2 * c + 1] = v.z;
                ws[(d + 3) * (2 * NBLK) + 2 * c] = v.w; ws[(d + 3) * (2 * NBLK) + 2 * c + 1] = v.w;
            }
        }
        __syncthreads();

        // ---- mainloop: 8 rows x 8 codes per thread, FFMA2 over packed row-pairs
        unsigned long long acc[4][8];
#pragma unroll
        for (int p = 0; p < 4; ++p)
#pragma unroll
            for (int j = 0; j < 8; ++j) acc[p][j] = 0ull;   // (0.f, 0.f)

        const float* px = xs + ty * TM;
        const float* pw = ws + tx * 16;
#pragma unroll 8
        for (int d = 0; d < DIM; ++d) {
            ulonglong2 xa = *(const ulonglong2*)(px);
            ulonglong2 xb = *(const ulonglong2*)(px + 4);
            ulonglong2 w0 = *(const ulonglong2*)(pw);
            ulonglong2 w1 = *(const ulonglong2*)(pw + 4);
            ulonglong2 w2 = *(const ulonglong2*)(pw + 8);
            ulonglong2 w3 = *(const ulonglong2*)(pw + 12);
            px += MBLK; pw += 2 * NBLK;
            unsigned long long xv[4] = {xa.x, xa.y, xb.x, xb.y};
            unsigned long long wv[8] = {w0.x, w0.y, w1.x, w1.y, w2.x, w2.y, w3.x, w3.y};
#pragma unroll
            for (int p = 0; p < 4; ++p)
#pragma unroll
                for (int j = 0; j < 8; ++j)
                    acc[p][j] = ffma2(xv[p], wv[j], acc[p][j]);
        }

        // ---- per-tile epilogue: distances + running argmin (codes ascending)
#pragma unroll
        for (int j = 0; j < 8; ++j) {
            int code = cb + tx * TN + j;
            float c2 = __ldg(&g_c2[code]);
#pragma unroll
            for (int p = 0; p < 4; ++p) {
                float lo = __uint_as_float((unsigned)(acc[p][j] & 0xffffffffull));
                float hi = __uint_as_float((unsigned)(acc[p][j] >> 32));
                int r0 = 2 * p, r1 = 2 * p + 1;
                float d0 = __fadd_rn(__fsub_rn(l2r[r0], __fmul_rn(2.0f, lo)), c2);
                float d1 = __fadd_rn(__fsub_rn(l2r[r1], __fmul_rn(2.0f, hi)), c2);
                if (d0 < bestd[r0]) { bestd[r0] = d0; besti[r0] = code; }
                if (d1 < bestd[r1]) { bestd[r1] = d1; besti[r1] = code; }
            }
        }
        __syncthreads();   // ws reuse next tile
    }

    // ---- cross-thread reduction over the 16 code groups (tx), padded stride 17
    float* redD = ws;                       // 128*17 floats
    int*   redI = (int*)(ws + 128 * 17);    // 128*17 ints
    int*   bidx = (int*)(ws + 2 * 128 * 17);
#pragma unroll
    for (int r = 0; r < TM; ++r) {
        int row = ty * TM + r;
        redD[row * 17 + tx] = bestd[r];
        redI[row * 17 + tx] = besti[r];
    }
    __syncthreads();

    if (tid < MBLK) {
        float bd = redD[tid * 17];
        int   bi = redI[tid * 17];
#pragma unroll
        for (int u = 1; u < 16; ++u) {
            float dv = redD[tid * 17 + u];
            int   iv = redI[tid * 17 + u];
            if (dv < bd || (dv == bd && iv < bi)) { bd = dv; bi = iv; }
        }
        bidx[tid] = bi;
        if (outI) outI[rowbase + tid] = (float)bi;
    }
    __syncthreads();

    // ---- gather quantized = W[closest]
    if (outQ) {
        int r = tid >> 1, h = tid & 1;
        int idx = bidx[r];
        const float4* src = (const float4*)(W + (size_t)idx * DIM + h * 32);
        float4* dst = (float4*)(outQ + (size_t)(rowbase + r) * DIM + h * 32);
#pragma unroll
        for (int q = 0; q < 8; ++q) dst[q] = __ldg(src + q);
    }
}

// ---------------------------------------------------------------------------
extern "C" void kernel_launch(void* const* d_in, const int* in_sizes, int n_in,
                              void* d_out, int out_size) {
    const float* X = (const float*)d_in[0];
    const float* W = (const float*)d_in[1];
    int N = in_sizes[0] / DIM;
    int K = in_sizes[1] / DIM;

    long long nd = (long long)N * DIM;
    float* outQ = nullptr;
    float* outI = nullptr;
    if ((long long)out_size >= nd + N) { outQ = (float*)d_out; outI = (float*)d_out + nd; }
    else if ((long long)out_size == nd) { outQ = (float*)d_out; }
    else { outI = (float*)d_out; }

    size_t smembytes = (size_t)(DIM * MBLK + DIM * 2 * NBLK + MBLK) * sizeof(float);
    cudaFuncSetAttribute(vq_kernel, cudaFuncAttributeMaxDynamicSharedMemorySize,
                         (int)smembytes);

    c2_kernel<<<(K + 255) / 256, 256>>>(W, K);
    vq_kernel<<<N / MBLK, 256, smembytes>>>(X, W, outQ, outI, K);
}

// round 7
// speedup vs baseline: 2.3069x; 2.3048x over previous
#include <cuda_runtime.h>
#include <cstdint>

// Problem constants (fixed by the reference): D=64, K=1024, N=65536.
#define DIM   64
#define MBLK  128          // rows per CTA
#define NBLK  128          // codes per smem tile
#define TM    8            // rows per thread
#define TN    8            // codes per thread
#define MAXK  4096

__device__ float g_c2[MAXK];   // ||w_k||^2, sequential fp32 sum

// Packed fp32x2 fused multiply-add (FFMA2). Each half is an IEEE fp32 FMA,
// so per-output accumulation chains are bit-identical to scalar fmaf chains.
__device__ __forceinline__ unsigned long long ffma2(unsigned long long a,
                                                    unsigned long long b,
                                                    unsigned long long c) {
    unsigned long long d;
    asm("fma.rn.f32x2 %0, %1, %2, %3;" : "=l"(d) : "l"(a), "l"(b), "l"(c));
    return d;
}

// ---------------------------------------------------------------------------
// C2[k] = sum_d W[k][d]^2, sequential (mul then add, round-to-nearest each op)
// ---------------------------------------------------------------------------
__global__ void c2_kernel(const float* __restrict__ W, int K) {
    int k = blockIdx.x * blockDim.x + threadIdx.x;
    if (k >= K) return;
    const float* w = W + k * DIM;
    float s = 0.0f;
#pragma unroll
    for (int d = 0; d < DIM; ++d)
        s = __fadd_rn(s, __fmul_rn(w[d], w[d]));
    g_c2[k] = s;
}

// ---------------------------------------------------------------------------
// Main VQ kernel: per-CTA 128 rows vs all K codes.
// dist = ((L2 - 2*dot) + C2) in fp32, argmin with first-index tie-break.
// ---------------------------------------------------------------------------
__global__ void __launch_bounds__(256, 2)
vq_kernel(const float* __restrict__ X, const float* __restrict__ W,
          float* __restrict__ outQ, float* __restrict__ outI, int K)
{
    extern __shared__ float smem[];
    float* xs  = smem;                               // [DIM][MBLK]      8192 f
    float* ws  = smem + DIM * MBLK;                  // [DIM][2*NBLK]   16384 f (dup codes)
    float* l2s = smem + DIM * MBLK + DIM * 2 * NBLK; // [MBLK]            128 f

    const int tid = threadIdx.x;
    const int tx  = tid & 15;        // code group
    const int ty  = tid >> 4;        // row group
    const int rowbase = blockIdx.x * MBLK;

    // ---- load X tile, transposed into xs[d][m] ----
    {
        int r = tid >> 1, h = tid & 1;
        const float4* src = (const float4*)(X + (size_t)(rowbase + r) * DIM + h * 32);
#pragma unroll
        for (int q = 0; q < 8; ++q) {
            float4 v = src[q];
            int d = h * 32 + q * 4;
            xs[(d + 0) * MBLK + r] = v.x;
            xs[(d + 1) * MBLK + r] = v.y;
            xs[(d + 2) * MBLK + r] = v.z;
            xs[(d + 3) * MBLK + r] = v.w;
        }
    }
    __syncthreads();

    // ---- L2 per row: sequential fp32 (mul, then add) ----
    if (tid < MBLK) {
        float s = 0.0f;
#pragma unroll
        for (int d = 0; d < DIM; ++d) {
            float v = xs[d * MBLK + tid];
            s = __fadd_rn(s, __fmul_rn(v, v));
        }
        l2s[tid] = s;
    }
    __syncthreads();

    float l2r[TM];
#pragma unroll
    for (int r = 0; r < TM; ++r) l2r[r] = l2s[ty * TM + r];

    float bestd[TM];
    int   besti[TM];
#pragma unroll
    for (int r = 0; r < TM; ++r) { bestd[r] = 3.4e38f; besti[r] = 0; }

    const int ntiles = K / NBLK;
    for (int t = 0; t < ntiles; ++t) {
        const int cb = t * NBLK;

        // ---- load W tile, transposed + duplicated: ws[d][2c]=ws[d][2c+1]=W[cb+c][d]
        // float2 stores (v,v): 2-way conflict max instead of 4-way scalar.
        {
            int c = tid >> 1, h = tid & 1;
            const float4* src = (const float4*)(W + (size_t)(cb + c) * DIM + h * 32);
            float2* wrow = (float2*)ws + c;          // column c (float2 index), row stride NBLK f2
#pragma unroll
            for (int q = 0; q < 8; ++q) {
                float4 v = src[q];
                int d = h * 32 + q * 4;
                wrow[(size_t)(d + 0) * NBLK] = make_float2(v.x, v.x);
                wrow[(size_t)(d + 1) * NBLK] = make_float2(v.y, v.y);
                wrow[(size_t)(d + 2) * NBLK] = make_float2(v.z, v.z);
                wrow[(size_t)(d + 3) * NBLK] = make_float2(v.w, v.w);
            }
        }
        __syncthreads();

        // ---- mainloop: 8 rows x 8 codes per thread, FFMA2 over packed row-pairs.
        // Thread tx owns codes {32q + 2tx, 32q + 2tx + 1 : q=0..3}: each W LDS.128
        // has lanes at bytes 16*tx + 256*q -> contiguous 256B, conflict-free.
        unsigned long long acc[4][8];
#pragma unroll
        for (int p = 0; p < 4; ++p)
#pragma unroll
            for (int j = 0; j < 8; ++j) acc[p][j] = 0ull;   // (0.f, 0.f)

        const float* px = xs + ty * TM;
        const float* pw = ws + tx * 4;
#pragma unroll 8
        for (int d = 0; d < DIM; ++d) {
            ulonglong2 xa = *(const ulonglong2*)(px);
            ulonglong2 xb = *(const ulonglong2*)(px + 4);
            ulonglong2 w0 = *(const ulonglong2*)(pw);            // codes 2tx, 2tx+1
            ulonglong2 w1 = *(const ulonglong2*)(pw + 64);       // codes 32+2tx, 32+2tx+1
            ulonglong2 w2 = *(const ulonglong2*)(pw + 128);      // codes 64+..
            ulonglong2 w3 = *(const ulonglong2*)(pw + 192);      // codes 96+..
            px += MBLK; pw += 2 * NBLK;
            unsigned long long xv[4] = {xa.x, xa.y, xb.x, xb.y};
            unsigned long long wv[8] = {w0.x, w0.y, w1.x, w1.y, w2.x, w2.y, w3.x, w3.y};
#pragma unroll
            for (int p = 0; p < 4; ++p)
#pragma unroll
                for (int j = 0; j < 8; ++j)
                    acc[p][j] = ffma2(xv[p], wv[j], acc[p][j]);
        }

        // ---- per-tile epilogue: distances + running argmin (codes ascending per thread)
#pragma unroll
        for (int j = 0; j < 8; ++j) {
            int code = cb + 32 * (j >> 1) + 2 * tx + (j & 1);
            float c2 = __ldg(&g_c2[code]);
#pragma unroll
            for (int p = 0; p < 4; ++p) {
                float lo = __uint_as_float((unsigned)(acc[p][j] & 0xffffffffull));
                float hi = __uint_as_float((unsigned)(acc[p][j] >> 32));
                int r0 = 2 * p, r1 = 2 * p + 1;
                float d0 = __fadd_rn(__fsub_rn(l2r[r0], __fmul_rn(2.0f, lo)), c2);
                float d1 = __fadd_rn(__fsub_rn(l2r[r1], __fmul_rn(2.0f, hi)), c2);
                if (d0 < bestd[r0]) { bestd[r0] = d0; besti[r0] = code; }
                if (d1 < bestd[r1]) { bestd[r1] = d1; besti[r1] = code; }
            }
        }
        __syncthreads();   // ws reuse next tile
    }

    // ---- cross-thread reduction over the 16 code groups (tx), padded stride 17.
    // Tie-break on smallest index handles the interleaved code ownership.
    float* redD = ws;                       // 128*17 floats
    int*   redI = (int*)(ws + 128 * 17);    // 128*17 ints
    int*   bidx = (int*)(ws + 2 * 128 * 17);
#pragma unroll
    for (int r = 0; r < TM; ++r) {
        int row = ty * TM + r;
        redD[row * 17 + tx] = bestd[r];
        redI[row * 17 + tx] = besti[r];
    }
    __syncthreads();

    if (tid < MBLK) {
        float bd = redD[tid * 17];
        int   bi = redI[tid * 17];
#pragma unroll
        for (int u = 1; u < 16; ++u) {
            float dv = redD[tid * 17 + u];
            int   iv = redI[tid * 17 + u];
            if (dv < bd || (dv == bd && iv < bi)) { bd = dv; bi = iv; }
        }
        bidx[tid] = bi;
        if (outI) outI[rowbase + tid] = (float)bi;
    }
    __syncthreads();

    // ---- gather quantized = W[closest]
    if (outQ) {
        int r = tid >> 1, h = tid & 1;
        int idx = bidx[r];
        const float4* src = (const float4*)(W + (size_t)idx * DIM + h * 32);
        float4* dst = (float4*)(outQ + (size_t)(rowbase + r) * DIM + h * 32);
#pragma unroll
        for (int q = 0; q < 8; ++q) dst[q] = __ldg(src + q);
    }
}

// ---------------------------------------------------------------------------
extern "C" void kernel_launch(void* const* d_in, const int* in_sizes, int n_in,
                              void* d_out, int out_size) {
    const float* X = (const float*)d_in[0];
    const float* W = (const float*)d_in[1];
    int N = in_sizes[0] / DIM;
    int K = in_sizes[1] / DIM;

    long long nd = (long long)N * DIM;
    float* outQ = nullptr;
    float* outI = nullptr;
    if ((long long)out_size >= nd + N) { outQ = (float*)d_out; outI = (float*)d_out + nd; }
    else if ((long long)out_size == nd) { outQ = (float*)d_out; }
    else { outI = (float*)d_out; }

    size_t smembytes = (size_t)(DIM * MBLK + DIM * 2 * NBLK + MBLK) * sizeof(float);
    cudaFuncSetAttribute(vq_kernel, cudaFuncAttributeMaxDynamicSharedMemorySize,
                         (int)smembytes);

    c2_kernel<<<(K + 255) / 256, 256>>>(W, K);
    vq_kernel<<<N / MBLK, 256, smembytes>>>(X, W, outQ, outI, K);
}

// round 8
// speedup vs baseline: 2.6162x; 1.1341x over previous
#include <cuda_runtime.h>
#include <cstdint>

// Problem constants (fixed by the reference): D=64, K=1024, N=65536.
#define DIM   64
#define MBLK  256          // rows per CTA
#define NBLK  128          // codes per smem tile
#define TM    16           // rows per thread (8 packed pairs)
#define TN    8            // codes per thread
#define MAXK  4096

__device__ float g_c2[MAXK];   // ||w_k||^2, sequential fp32 sum

// Packed fp32x2 fused multiply-add (FFMA2). Each half is an IEEE fp32 FMA,
// so per-output accumulation chains are bit-identical to scalar fmaf chains.
__device__ __forceinline__ unsigned long long ffma2(unsigned long long a,
                                                    unsigned long long b,
                                                    unsigned long long c) {
    unsigned long long d;
    asm("fma.rn.f32x2 %0, %1, %2, %3;" : "=l"(d) : "l"(a), "l"(b), "l"(c));
    return d;
}

// ---------------------------------------------------------------------------
// C2[k] = sum_d W[k][d]^2, sequential (mul then add, round-to-nearest each op)
// ---------------------------------------------------------------------------
__global__ void c2_kernel(const float* __restrict__ W, int K) {
    int k = blockIdx.x * blockDim.x + threadIdx.x;
    if (k >= K) return;
    const float* w = W + k * DIM;
    float s = 0.0f;
#pragma unroll
    for (int d = 0; d < DIM; ++d)
        s = __fadd_rn(s, __fmul_rn(w[d], w[d]));
    g_c2[k] = s;
}

// ---------------------------------------------------------------------------
// Main VQ kernel: per-CTA 256 rows vs all K codes.
// dist = ((L2 - 2*dot) + C2) in fp32, argmin with first-index tie-break.
// ---------------------------------------------------------------------------
__global__ void __launch_bounds__(256, 1)
vq_kernel(const float* __restrict__ X, const float* __restrict__ W,
          float* __restrict__ outQ, float* __restrict__ outI, int K)
{
    extern __shared__ float smem[];
    float* xs  = smem;                               // [DIM][MBLK]     16384 f (64 KB)
    float* ws  = smem + DIM * MBLK;                  // [DIM][2*NBLK]   16384 f (64 KB, dup)
    float* l2s = smem + DIM * MBLK + DIM * 2 * NBLK; // [MBLK]            256 f

    const int tid = threadIdx.x;
    const int tx  = tid & 15;        // code group
    const int ty  = tid >> 4;        // row group (16 rows each)
    const int rowbase = blockIdx.x * MBLK;

    // ---- load X tile, transposed into xs[d][m]: one full row per thread ----
    {
        const float4* src = (const float4*)(X + (size_t)(rowbase + tid) * DIM);
#pragma unroll
        for (int q = 0; q < 16; ++q) {
            float4 v = src[q];
            int d = q * 4;
            xs[(d + 0) * MBLK + tid] = v.x;
            xs[(d + 1) * MBLK + tid] = v.y;
            xs[(d + 2) * MBLK + tid] = v.z;
            xs[(d + 3) * MBLK + tid] = v.w;
        }
    }
    __syncthreads();

    // ---- L2 per row: sequential fp32 (mul, then add) ----
    {
        float s = 0.0f;
#pragma unroll
        for (int d = 0; d < DIM; ++d) {
            float v = xs[d * MBLK + tid];
            s = __fadd_rn(s, __fmul_rn(v, v));
        }
        l2s[tid] = s;
    }
    __syncthreads();

    float bestd[TM];
    int   besti[TM];
#pragma unroll
    for (int r = 0; r < TM; ++r) { bestd[r] = 3.4e38f; besti[r] = 0; }

    const int ntiles = K / NBLK;
    for (int t = 0; t < ntiles; ++t) {
        const int cb = t * NBLK;

        // ---- load W tile, transposed + duplicated: ws[d][2c]=ws[d][2c+1]=W[cb+c][d]
        {
            int c = tid >> 1, h = tid & 1;
            const float4* src = (const float4*)(W + (size_t)(cb + c) * DIM + h * 32);
            float2* wrow = (float2*)ws + c;          // column c (float2 idx), row stride NBLK f2
#pragma unroll
            for (int q = 0; q < 8; ++q) {
                float4 v = src[q];
                int d = h * 32 + q * 4;
                wrow[(size_t)(d + 0) * NBLK] = make_float2(v.x, v.x);
                wrow[(size_t)(d + 1) * NBLK] = make_float2(v.y, v.y);
                wrow[(size_t)(d + 2) * NBLK] = make_float2(v.z, v.z);
                wrow[(size_t)(d + 3) * NBLK] = make_float2(v.w, v.w);
            }
        }
        __syncthreads();

        // ---- mainloop: 16 rows (8 pairs) x 8 codes per thread, FFMA2.
        // W: thread tx owns codes {32q + 2tx, 32q + 2tx + 1 : q=0..3}; each W LDS.128
        // reads bytes 16*tx + 256*q -> contiguous 256B across 16 lanes, conflict-free.
        // X: 4 LDS.128 broadcast within each 16-lane half-warp.
        unsigned long long acc[8][8];
#pragma unroll
        for (int p = 0; p < 8; ++p)
#pragma unroll
            for (int j = 0; j < 8; ++j) acc[p][j] = 0ull;   // (0.f, 0.f)

        const float* px = xs + ty * TM;
        const float* pw = ws + tx * 4;
#pragma unroll 4
        for (int d = 0; d < DIM; ++d) {
            ulonglong2 xa = *(const ulonglong2*)(px);
            ulonglong2 xb = *(const ulonglong2*)(px + 4);
            ulonglong2 xc = *(const ulonglong2*)(px + 8);
            ulonglong2 xd = *(const ulonglong2*)(px + 12);
            ulonglong2 w0 = *(const ulonglong2*)(pw);            // codes 2tx, 2tx+1
            ulonglong2 w1 = *(const ulonglong2*)(pw + 64);       // codes 32+2tx, 33+2tx
            ulonglong2 w2 = *(const ulonglong2*)(pw + 128);      // codes 64+..
            ulonglong2 w3 = *(const ulonglong2*)(pw + 192);      // codes 96+..
            px += MBLK; pw += 2 * NBLK;
            unsigned long long xv[8] = {xa.x, xa.y, xb.x, xb.y, xc.x, xc.y, xd.x, xd.y};
            unsigned long long wv[8] = {w0.x, w0.y, w1.x, w1.y, w2.x, w2.y, w3.x, w3.y};
#pragma unroll
            for (int p = 0; p < 8; ++p)
#pragma unroll
                for (int j = 0; j < 8; ++j)
                    acc[p][j] = ffma2(xv[p], wv[j], acc[p][j]);
        }

        // ---- per-tile epilogue: distances + running argmin (codes ascending per thread)
#pragma unroll
        for (int j = 0; j < 8; ++j) {
            int code = cb + 32 * (j >> 1) + 2 * tx + (j & 1);
            float c2 = __ldg(&g_c2[code]);
#pragma unroll
            for (int p = 0; p < 8; ++p) {
                float lo = __uint_as_float((unsigned)(acc[p][j] & 0xffffffffull));
                float hi = __uint_as_float((unsigned)(acc[p][j] >> 32));
                int r0 = 2 * p, r1 = 2 * p + 1;
                float el0 = l2s[ty * TM + r0];
                float el1 = l2s[ty * TM + r1];
                float d0 = __fadd_rn(__fsub_rn(el0, __fmul_rn(2.0f, lo)), c2);
                float d1 = __fadd_rn(__fsub_rn(el1, __fmul_rn(2.0f, hi)), c2);
                if (d0 < bestd[r0]) { bestd[r0] = d0; besti[r0] = code; }
                if (d1 < bestd[r1]) { bestd[r1] = d1; besti[r1] = code; }
            }
        }
        __syncthreads();   // ws reuse next tile
    }

    // ---- cross-thread reduction over the 16 code groups (tx), padded stride 17.
    // Tie-break on smallest index handles the interleaved code ownership.
    float* redD = ws;                         // 256*17 floats
    int*   redI = (int*)(ws + 256 * 17);      // 256*17 ints
    int*   bidx = (int*)(ws + 2 * 256 * 17);  // 256 ints
#pragma unroll
    for (int r = 0; r < TM; ++r) {
        int row = ty * TM + r;
        redD[row * 17 + tx] = bestd[r];
        redI[row * 17 + tx] = besti[r];
    }
    __syncthreads();

    {
        float bd = redD[tid * 17];
        int   bi = redI[tid * 17];
#pragma unroll
        for (int u = 1; u < 16; ++u) {
            float dv = redD[tid * 17 + u];
            int   iv = redI[tid * 17 + u];
            if (dv < bd || (dv == bd && iv < bi)) { bd = dv; bi = iv; }
        }
        bidx[tid] = bi;
        if (outI) outI[rowbase + tid] = (float)bi;
    }
    __syncthreads();

    // ---- gather quantized = W[closest]: one row per thread
    if (outQ) {
        int idx = bidx[tid];
        const float4* src = (const float4*)(W + (size_t)idx * DIM);
        float4* dst = (float4*)(outQ + (size_t)(rowbase + tid) * DIM);
#pragma unroll
        for (int q = 0; q < 16; ++q) dst[q] = __ldg(src + q);
    }
}

// ---------------------------------------------------------------------------
extern "C" void kernel_launch(void* const* d_in, const int* in_sizes, int n_in,
                              void* d_out, int out_size) {
    const float* X = (const float*)d_in[0];
    const float* W = (const float*)d_in[1];
    int N = in_sizes[0] / DIM;
    int K = in_sizes[1] / DIM;

    long long nd = (long long)N * DIM;
    float* outQ = nullptr;
    float* outI = nullptr;
    if ((long long)out_size >= nd + N) { outQ = (float*)d_out; outI = (float*)d_out + nd; }
    else if ((long long)out_size == nd) { outQ = (float*)d_out; }
    else { outI = (float*)d_out; }

    size_t smembytes = (size_t)(DIM * MBLK + DIM * 2 * NBLK + MBLK) * sizeof(float);
    cudaFuncSetAttribute(vq_kernel, cudaFuncAttributeMaxDynamicSharedMemorySize,
                         (int)smembytes);

    c2_kernel<<<(K + 255) / 256, 256>>>(W, K);
    vq_kernel<<<N / MBLK, 256, smembytes>>>(X, W, outQ, outI, K);
}